// round 7
// baseline (speedup 1.0000x reference)
#include <cuda_runtime.h>
#include <cuda_bf16.h>
#include <math.h>

#define NN   20000
#define FIN  128
#define HID  32
#define HEADS 8
#define HC   256
#define EE   320000
#define ETOT 340000
#define GG   64
#define CLS  10

// ---------------- scratch (static device globals; no allocation) ----------------
__device__ float    g_h[NN * HC];
__device__ float    g_x1[NN * HC];
__device__ float    g_out2[NN * HC];
__device__ float    g_alpha[ETOT * HEADS];
__device__ unsigned g_amax[NN * HEADS];
__device__ float    g_denom[NN * HEADS];
__device__ float    g_al[NN * HEADS];
__device__ float    g_ar[NN * HEADS];
__device__ int      g_deg[NN];
__device__ int      g_cursor[NN];
__device__ int      g_rowptr[NN + 1];
__device__ int      g_srcs[ETOT];
__device__ int      g_eids[ETOT];
__device__ float    g_sums[GG * HC];
__device__ int      g_cnt[GG];
__device__ int      g_is64;     // 1 if index buffers are int64, 0 if int32

// ---------------- dtype detection ----------------
// Index values are < 20000 < 2^31. If the buffer really holds int64, every
// high 32-bit word is 0. If the harness downcast to int32, the odd words are
// random indices — the OR over 64 of them is nonzero with overwhelming prob.
__global__ void detect_kernel(const void* ei) {
    const int* p = (const int*)ei;
    int or_hi = 0;
    #pragma unroll
    for (int i = 0; i < 64; i++) or_hi |= p[2 * i + 1];
    g_is64 = (or_hi == 0) ? 1 : 0;
}

// ---------------- helpers ----------------
__device__ __forceinline__ unsigned enc_f(float f) {
    unsigned u = __float_as_uint(f);
    return (u & 0x80000000u) ? ~u : (u | 0x80000000u);
}
__device__ __forceinline__ float dec_f(unsigned k) {
    return (k & 0x80000000u) ? __uint_as_float(k ^ 0x80000000u) : __uint_as_float(~k);
}
__device__ __forceinline__ int idx_at(const void* p, int i) {
    if (g_is64) return (int)((const long long*)p)[i];
    return ((const int*)p)[i];
}
__device__ __forceinline__ void edge_sd(const void* ei, int e, int& s, int& d) {
    if (e < EE) { s = idx_at(ei, e); d = idx_at(ei, EE + e); }
    else        { s = e - EE; d = e - EE; }
}
__device__ __forceinline__ int edge_dst(const void* ei, int e) {
    return (e < EE) ? idx_at(ei, EE + e) : (e - EE);
}

// ---------------- zero kernels ----------------
__global__ void zero_csr_kernel() {
    int i = blockIdx.x * blockDim.x + threadIdx.x;
    if (i < NN) { g_deg[i] = 0; g_cursor[i] = 0; }
}
__global__ void zero_softmax_kernel() {
    int i = blockIdx.x * blockDim.x + threadIdx.x;
    if (i < NN * HEADS) { g_amax[i] = 0u; g_denom[i] = 0.f; }
}

// ---------------- CSR build ----------------
__global__ void degree_kernel(const void* __restrict__ ei) {
    int e = blockIdx.x * blockDim.x + threadIdx.x;
    if (e >= ETOT) return;
    atomicAdd(&g_deg[edge_dst(ei, e)], 1);
}

__global__ void scan_kernel() {
    __shared__ int ssum[1024];
    const int CH = 20;
    int t = threadIdx.x;
    int base = t * CH;
    int local[CH];
    int s = 0;
    #pragma unroll
    for (int i = 0; i < CH; i++) {
        int idx = base + i;
        int v = (idx < NN) ? g_deg[idx] : 0;
        local[i] = s; s += v;
    }
    ssum[t] = s;
    __syncthreads();
    for (int off = 1; off < 1024; off <<= 1) {
        int v = (t >= off) ? ssum[t - off] : 0;
        __syncthreads();
        ssum[t] += v;
        __syncthreads();
    }
    int excl = (t > 0) ? ssum[t - 1] : 0;
    #pragma unroll
    for (int i = 0; i < CH; i++) {
        int idx = base + i;
        if (idx < NN) g_rowptr[idx] = excl + local[i];
    }
    if (t == 1023) g_rowptr[NN] = ssum[1023];
}

__global__ void scatter_kernel(const void* __restrict__ ei) {
    int e = blockIdx.x * blockDim.x + threadIdx.x;
    if (e >= ETOT) return;
    int s, d; edge_sd(ei, e, s, d);
    int pos = atomicAdd(&g_cursor[d], 1);
    int idx = g_rowptr[d] + pos;
    g_srcs[idx] = s;
    g_eids[idx] = e;
}

// ---------------- GEMM into g_h: g_h[M,256] = A[M,K] @ B[K,256] ----------------
#define BM 64
#define BN 64
#define BK 16
__global__ void gemm_h_kernel(const float* __restrict__ Aext, const float* __restrict__ B,
                              int M, int K, int use_x1) {
    __shared__ float As[BK][BM + 1];
    __shared__ float Bs[BK][BN + 1];
    const float* A = use_x1 ? (const float*)g_x1 : Aext;
    int tid = threadIdx.x;
    int tx = tid & 15, ty = tid >> 4;
    int row0 = blockIdx.y * BM, col0 = blockIdx.x * BN;
    float acc[4][4] = {};
    for (int k0 = 0; k0 < K; k0 += BK) {
        #pragma unroll
        for (int i = 0; i < 4; i++) {
            int idx = tid + i * 256;
            int r = idx >> 4, kk = idx & 15;
            int gr = row0 + r;
            As[kk][r] = (gr < M) ? A[(long)gr * K + k0 + kk] : 0.f;
        }
        #pragma unroll
        for (int i = 0; i < 4; i++) {
            int idx = tid + i * 256;
            int kk = idx >> 6, c = idx & 63;
            Bs[kk][c] = B[(long)(k0 + kk) * HC + col0 + c];
        }
        __syncthreads();
        #pragma unroll
        for (int kk = 0; kk < BK; kk++) {
            float ra[4], rb[4];
            #pragma unroll
            for (int i = 0; i < 4; i++) ra[i] = As[kk][ty * 4 + i];
            #pragma unroll
            for (int j = 0; j < 4; j++) rb[j] = Bs[kk][tx * 4 + j];
            #pragma unroll
            for (int i = 0; i < 4; i++)
                #pragma unroll
                for (int j = 0; j < 4; j++)
                    acc[i][j] += ra[i] * rb[j];
        }
        __syncthreads();
    }
    #pragma unroll
    for (int i = 0; i < 4; i++) {
        int r = row0 + ty * 4 + i;
        if (r < M) {
            #pragma unroll
            for (int j = 0; j < 4; j++)
                g_h[(long)r * HC + col0 + tx * 4 + j] = acc[i][j];
        }
    }
}

// ---------------- per-node att_l / att_r dots ----------------
__global__ void alr_kernel(const float* __restrict__ att_l, const float* __restrict__ att_r) {
    int warp = (blockIdx.x * blockDim.x + threadIdx.x) >> 5;
    int lane = threadIdx.x & 31;
    if (warp >= NN) return;
    const float* hv = g_h + (long)warp * HC;
    #pragma unroll
    for (int h = 0; h < HEADS; h++) {
        float a = hv[h * HID + lane];
        float dl = a * att_l[h * HID + lane];
        float dr = a * att_r[h * HID + lane];
        #pragma unroll
        for (int o = 16; o; o >>= 1) {
            dl += __shfl_xor_sync(0xffffffffu, dl, o);
            dr += __shfl_xor_sync(0xffffffffu, dr, o);
        }
        if (lane == 0) { g_al[warp * HEADS + h] = dl; g_ar[warp * HEADS + h] = dr; }
    }
}

// ---------------- edge alpha: logits dot + alpha + segment max ----------------
__global__ void edge_alpha_kernel(const void* __restrict__ ei) {
    int warp = (blockIdx.x * blockDim.x + threadIdx.x) >> 5;
    int lane = threadIdx.x & 31;
    if (warp >= ETOT) return;
    int s, d; edge_sd(ei, warp, s, d);
    const float* hs = g_h + (long)s * HC;
    const float* hd = g_h + (long)d * HC;
    #pragma unroll
    for (int h = 0; h < HEADS; h++) {
        float dot = hs[h * HID + lane] * hd[h * HID + lane];
        #pragma unroll
        for (int o = 16; o; o >>= 1) dot += __shfl_xor_sync(0xffffffffu, dot, o);
        if (lane == 0) {
            float a = g_al[s * HEADS + h] + g_ar[d * HEADS + h];
            float sg = 1.f / (1.f + expf(-dot));
            a *= sg;
            a = a > 0.f ? a : 0.2f * a;
            g_alpha[warp * HEADS + h] = a;
            atomicMax(&g_amax[d * HEADS + h], enc_f(a));
        }
    }
}

// ---------------- exp + segment sum ----------------
__global__ void edge_exp_kernel(const void* __restrict__ ei) {
    int idx = blockIdx.x * blockDim.x + threadIdx.x;
    if (idx >= ETOT * HEADS) return;
    int e = idx >> 3, h = idx & 7;
    int d = edge_dst(ei, e);
    float m = dec_f(g_amax[d * HEADS + h]);
    float ex = expf(g_alpha[idx] - m);
    g_alpha[idx] = ex;
    atomicAdd(&g_denom[d * HEADS + h], ex);
}

// ---------------- aggregation (CSR, block per dst) ----------------
// mode 1: write elu(acc+b) into g_x1 ; mode 0: write acc+b into g_out2
__global__ void aggregate_kernel(const float* __restrict__ b, int mode) {
    int v = blockIdx.x;
    int tid = threadIdx.x;
    int hh = tid >> 5;
    __shared__ float sh_rd[HEADS];
    if (tid < HEADS) sh_rd[tid] = 1.f / (g_denom[v * HEADS + tid] + 1e-16f);
    __syncthreads();
    float rd = sh_rd[hh];
    int i = g_rowptr[v], end = g_rowptr[v + 1];
    float acc0 = 0.f, acc1 = 0.f;
    for (; i + 1 < end; i += 2) {
        int sA = g_srcs[i],     eA = g_eids[i];
        int sB = g_srcs[i + 1], eB = g_eids[i + 1];
        float wA = g_alpha[eA * HEADS + hh] * rd;
        float wB = g_alpha[eB * HEADS + hh] * rd;
        acc0 += g_h[(long)sA * HC + tid] * wA;
        acc1 += g_h[(long)sB * HC + tid] * wB;
    }
    if (i < end) {
        int sA = g_srcs[i], eA = g_eids[i];
        acc0 += g_h[(long)sA * HC + tid] * (g_alpha[eA * HEADS + hh] * rd);
    }
    float r = acc0 + acc1 + b[tid];
    if (mode) {
        r = r > 0.f ? r : expm1f(r);
        g_x1[(long)v * HC + tid] = r;
    } else {
        g_out2[(long)v * HC + tid] = r;
    }
}

// ---------------- pooling (sorted batch, binary search) ----------------
__device__ __forceinline__ int lbound_idx(const void* a, int n, int key) {
    int lo = 0, hi = n;
    while (lo < hi) {
        int mid = (lo + hi) >> 1;
        if (idx_at(a, mid) < key) lo = mid + 1; else hi = mid;
    }
    return lo;
}
__global__ void pool_kernel(const void* __restrict__ batch) {
    int g = blockIdx.x;
    int tid = threadIdx.x;
    int lo = lbound_idx(batch, NN, g);
    int hi = lbound_idx(batch, NN, g + 1);
    float acc = 0.f;
    for (int n = lo; n < hi; n++) acc += g_out2[(long)n * HC + tid];
    g_sums[g * HC + tid] = acc;
    if (tid == 0) g_cnt[g] = hi - lo;
}

// ---------------- final linear ----------------
__global__ void final_kernel(const float* __restrict__ linW, const float* __restrict__ linb,
                             float* __restrict__ out) {
    int g = blockIdx.x;
    int tid = threadIdx.x;
    int lane = tid & 31, w = tid >> 5;
    __shared__ float sw[8][CLS];
    float cnt = fmaxf((float)g_cnt[g], 1.f);
    float v = g_sums[g * HC + tid] / cnt;
    #pragma unroll
    for (int c = 0; c < CLS; c++) {
        float t = v * linW[tid * CLS + c];
        #pragma unroll
        for (int o = 16; o; o >>= 1) t += __shfl_xor_sync(0xffffffffu, t, o);
        if (lane == 0) sw[w][c] = t;
    }
    __syncthreads();
    if (tid < CLS) {
        float s = 0.f;
        #pragma unroll
        for (int ww = 0; ww < 8; ww++) s += sw[ww][tid];
        out[g * CLS + tid] = s + linb[tid];
    }
}

// ---------------- launch ----------------
extern "C" void kernel_launch(void* const* d_in, const int* in_sizes, int n_in,
                              void* d_out, int out_size) {
    // Bind inputs BY ELEMENT COUNT (robust to ordering surprises). The six
    // 256-element params are taken in encounter order: att_l1, att_r1, b1,
    // att_l2, att_r2, b2 — matching the reference setup_inputs order.
    const float* x = nullptr;
    const void*  ei = nullptr;
    const void*  batch = nullptr;
    const float *W1 = nullptr, *W2 = nullptr, *linW = nullptr, *linb = nullptr;
    const float* p256[6] = {};
    int n256 = 0;
    for (int i = 0; i < n_in; i++) {
        switch (in_sizes[i]) {
            case NN * FIN: x    = (const float*)d_in[i]; break;   // 2,560,000
            case 2 * EE:   ei   = d_in[i];               break;   // 640,000
            case NN:       batch = d_in[i];              break;   // 20,000
            case FIN * HC: W1   = (const float*)d_in[i]; break;   // 32,768
            case HC * HC:  W2   = (const float*)d_in[i]; break;   // 65,536
            case HC * CLS: linW = (const float*)d_in[i]; break;   // 2,560
            case CLS:      linb = (const float*)d_in[i]; break;   // 10
            case HC:       if (n256 < 6) p256[n256++] = (const float*)d_in[i]; break;
            default: break;
        }
    }
    const float* att_l1 = p256[0];
    const float* att_r1 = p256[1];
    const float* b1     = p256[2];
    const float* att_l2 = p256[3];
    const float* att_r2 = p256[4];
    const float* b2     = p256[5];
    float* out = (float*)d_out;
    (void)out_size;

    const int T = 256;
    dim3 ggrid(HC / BN, (NN + BM - 1) / BM);

    // dtype probe (int32 vs int64 index buffers)
    detect_kernel<<<1, 1>>>(ei);

    // CSR build (shared by both layers)
    zero_csr_kernel<<<(NN + T - 1) / T, T>>>();
    degree_kernel<<<(ETOT + T - 1) / T, T>>>(ei);
    scan_kernel<<<1, 1024>>>();
    scatter_kernel<<<(ETOT + T - 1) / T, T>>>(ei);

    // ---- layer 1 ----
    gemm_h_kernel<<<ggrid, 256>>>(x, W1, NN, FIN, 0);
    zero_softmax_kernel<<<(NN * HEADS + T - 1) / T, T>>>();
    alr_kernel<<<(NN * 32 + T - 1) / T, T>>>(att_l1, att_r1);
    edge_alpha_kernel<<<(ETOT * 32 + T - 1) / T, T>>>(ei);
    edge_exp_kernel<<<(ETOT * HEADS + T - 1) / T, T>>>(ei);
    aggregate_kernel<<<NN, 256>>>(b1, 1);

    // ---- layer 2 ----
    gemm_h_kernel<<<ggrid, 256>>>(nullptr, W2, NN, HC, 1);
    zero_softmax_kernel<<<(NN * HEADS + T - 1) / T, T>>>();
    alr_kernel<<<(NN * 32 + T - 1) / T, T>>>(att_l2, att_r2);
    edge_alpha_kernel<<<(ETOT * 32 + T - 1) / T, T>>>(ei);
    edge_exp_kernel<<<(ETOT * HEADS + T - 1) / T, T>>>(ei);
    aggregate_kernel<<<NN, 256>>>(b2, 0);

    // ---- pool + classify ----
    pool_kernel<<<GG, HC>>>(batch);
    final_kernel<<<GG, HC>>>(linW, linb, out);
}

// round 10
// speedup vs baseline: 1.4841x; 1.4841x over previous
#include <cuda_runtime.h>
#include <cuda_bf16.h>
#include <math.h>

#define NN   20000
#define FIN  128
#define HID  32
#define HEADS 8
#define HC   256
#define EE   320000
#define ETOT 340000
#define GG   64
#define CLS  10

// ---------------- scratch (static device globals; no allocation) ----------------
__device__ __align__(16) float g_h[NN * HC];
__device__ __align__(16) float g_x1[NN * HC];
__device__ __align__(16) float g_out2[NN * HC];
__device__ float    g_alpha[ETOT * HEADS];   // raw leaky-relu'd alpha (pre-softmax)
__device__ unsigned g_amax[NN * HEADS];
__device__ float    g_al[NN * HEADS];
__device__ float    g_ar[NN * HEADS];
__device__ int      g_deg[NN];
__device__ int      g_cursor[NN];
__device__ int      g_rowptr[NN + 1];
__device__ int      g_srcs[ETOT];
__device__ int      g_eids[ETOT];
__device__ float    g_sums[GG * HC];
__device__ int      g_cnt[GG];
__device__ int      g_is64;

// ---------------- dtype detection (int64 vs int32 index buffers) ----------------
__global__ void detect_kernel(const void* ei) {
    const int* p = (const int*)ei;
    int or_hi = 0;
    #pragma unroll
    for (int i = 0; i < 64; i++) or_hi |= p[2 * i + 1];
    g_is64 = (or_hi == 0) ? 1 : 0;
}

// ---------------- helpers ----------------
__device__ __forceinline__ unsigned enc_f(float f) {
    unsigned u = __float_as_uint(f);
    return (u & 0x80000000u) ? ~u : (u | 0x80000000u);
}
__device__ __forceinline__ float dec_f(unsigned k) {
    return (k & 0x80000000u) ? __uint_as_float(k ^ 0x80000000u) : __uint_as_float(~k);
}
__device__ __forceinline__ int idx_at(const void* p, int i) {
    if (g_is64) return (int)((const long long*)p)[i];
    return ((const int*)p)[i];
}
__device__ __forceinline__ void edge_sd(const void* ei, int e, int& s, int& d) {
    if (e < EE) { s = idx_at(ei, e); d = idx_at(ei, EE + e); }
    else        { s = e - EE; d = e - EE; }
}
__device__ __forceinline__ int edge_dst(const void* ei, int e) {
    return (e < EE) ? idx_at(ei, EE + e) : (e - EE);
}

// ---------------- zero kernels ----------------
__global__ void zero_csr_kernel() {
    int i = blockIdx.x * blockDim.x + threadIdx.x;
    if (i < NN) { g_deg[i] = 0; g_cursor[i] = 0; }
}
__global__ void zero_amax_kernel() {
    int i = blockIdx.x * blockDim.x + threadIdx.x;
    if (i < NN * HEADS) g_amax[i] = 0u;
}

// ---------------- CSR build ----------------
__global__ void degree_kernel(const void* __restrict__ ei) {
    int e = blockIdx.x * blockDim.x + threadIdx.x;
    if (e >= ETOT) return;
    atomicAdd(&g_deg[edge_dst(ei, e)], 1);
}

// shfl-based scan: 1024 threads x 20 items
__global__ void scan_kernel() {
    __shared__ int warp_sums[32];
    const int CH = 20;
    int t = threadIdx.x;
    int lane = t & 31, w = t >> 5;
    int base = t * CH;
    int local[CH];
    int s = 0;
    #pragma unroll
    for (int i = 0; i < CH; i++) {
        int idx = base + i;
        int v = (idx < NN) ? g_deg[idx] : 0;
        local[i] = s; s += v;
    }
    int ss = s;  // inclusive warp scan of per-thread totals
    #pragma unroll
    for (int o = 1; o < 32; o <<= 1) {
        int vv = __shfl_up_sync(0xffffffffu, ss, o);
        if (lane >= o) ss += vv;
    }
    if (lane == 31) warp_sums[w] = ss;
    __syncthreads();
    if (w == 0) {
        int x = warp_sums[lane];
        #pragma unroll
        for (int o = 1; o < 32; o <<= 1) {
            int vv = __shfl_up_sync(0xffffffffu, x, o);
            if (lane >= o) x += vv;
        }
        warp_sums[lane] = x;
    }
    __syncthreads();
    int excl = ((w > 0) ? warp_sums[w - 1] : 0) + ss - s;
    #pragma unroll
    for (int i = 0; i < CH; i++) {
        int idx = base + i;
        if (idx < NN) g_rowptr[idx] = excl + local[i];
    }
    if (t == 1023) g_rowptr[NN] = warp_sums[31];
}

__global__ void scatter_kernel(const void* __restrict__ ei) {
    int e = blockIdx.x * blockDim.x + threadIdx.x;
    if (e >= ETOT) return;
    int s, d; edge_sd(ei, e, s, d);
    int pos = atomicAdd(&g_cursor[d], 1);
    int idx = g_rowptr[d] + pos;
    g_srcs[idx] = s;
    g_eids[idx] = e;
}

// ---------------- GEMM into g_h: g_h[M,256] = A[M,K] @ B[K,256] ----------------
// 128x64 tile, 256 threads, 8x4 accumulators per thread.
#define BM 128
#define BN 64
#define BK 16
__global__ void gemm_h_kernel(const float* __restrict__ Aext, const float* __restrict__ B,
                              int M, int K, int use_x1) {
    __shared__ float As[BK][BM + 4];
    __shared__ float Bs[BK][BN + 4];
    const float* A = use_x1 ? (const float*)g_x1 : Aext;
    int tid = threadIdx.x;
    int tx = tid & 15, ty = tid >> 4;
    int row0 = blockIdx.y * BM, col0 = blockIdx.x * BN;
    float acc[8][4] = {};
    for (int k0 = 0; k0 < K; k0 += BK) {
        #pragma unroll
        for (int i = 0; i < 8; i++) {           // 2048 A elems
            int idx = tid + i * 256;
            int r = idx >> 4, kk = idx & 15;
            int gr = row0 + r;
            As[kk][r] = (gr < M) ? A[(long)gr * K + k0 + kk] : 0.f;
        }
        #pragma unroll
        for (int i = 0; i < 4; i++) {           // 1024 B elems
            int idx = tid + i * 256;
            int kk = idx >> 6, c = idx & 63;
            Bs[kk][c] = B[(long)(k0 + kk) * HC + col0 + c];
        }
        __syncthreads();
        #pragma unroll
        for (int kk = 0; kk < BK; kk++) {
            float ra[8], rb[4];
            #pragma unroll
            for (int i = 0; i < 8; i++) ra[i] = As[kk][ty * 8 + i];
            #pragma unroll
            for (int j = 0; j < 4; j++) rb[j] = Bs[kk][tx * 4 + j];
            #pragma unroll
            for (int i = 0; i < 8; i++)
                #pragma unroll
                for (int j = 0; j < 4; j++)
                    acc[i][j] += ra[i] * rb[j];
        }
        __syncthreads();
    }
    #pragma unroll
    for (int i = 0; i < 8; i++) {
        int r = row0 + ty * 8 + i;
        if (r < M) {
            float4 v = make_float4(acc[i][0], acc[i][1], acc[i][2], acc[i][3]);
            *(float4*)&g_h[(long)r * HC + col0 + tx * 4] = v;
        }
    }
}

// ---------------- per-node att_l / att_r dots (vectorized) ----------------
// Lane L holds elements [8L, 8L+8) -> always within head L>>2. 2 shuffle rounds.
__global__ void alr_kernel(const float* __restrict__ att_l, const float* __restrict__ att_r) {
    int warp = (blockIdx.x * blockDim.x + threadIdx.x) >> 5;
    int lane = threadIdx.x & 31;
    if (warp >= NN) return;
    const float4* hv = (const float4*)(g_h + (long)warp * HC);
    const float4* al = (const float4*)att_l;
    const float4* ar = (const float4*)att_r;
    float4 h0 = hv[2 * lane], h1 = hv[2 * lane + 1];
    float4 l0 = al[2 * lane], l1 = al[2 * lane + 1];
    float4 r0 = ar[2 * lane], r1 = ar[2 * lane + 1];
    float dl = h0.x * l0.x + h0.y * l0.y + h0.z * l0.z + h0.w * l0.w
             + h1.x * l1.x + h1.y * l1.y + h1.z * l1.z + h1.w * l1.w;
    float dr = h0.x * r0.x + h0.y * r0.y + h0.z * r0.z + h0.w * r0.w
             + h1.x * r1.x + h1.y * r1.y + h1.z * r1.z + h1.w * r1.w;
    dl += __shfl_xor_sync(0xffffffffu, dl, 1);
    dl += __shfl_xor_sync(0xffffffffu, dl, 2);
    dr += __shfl_xor_sync(0xffffffffu, dr, 1);
    dr += __shfl_xor_sync(0xffffffffu, dr, 2);
    if ((lane & 3) == 0) {
        int h = lane >> 2;
        g_al[warp * HEADS + h] = dl;
        g_ar[warp * HEADS + h] = dr;
    }
}

// ---------------- edge alpha: logits dot + alpha + segment max (vectorized) ----------------
__global__ void edge_alpha_kernel(const void* __restrict__ ei) {
    int warp = (blockIdx.x * blockDim.x + threadIdx.x) >> 5;
    int lane = threadIdx.x & 31;
    if (warp >= ETOT) return;
    int s, d; edge_sd(ei, warp, s, d);
    const float4* hs = (const float4*)(g_h + (long)s * HC);
    const float4* hd = (const float4*)(g_h + (long)d * HC);
    float4 a0 = hs[2 * lane], a1 = hs[2 * lane + 1];
    float4 b0 = hd[2 * lane], b1 = hd[2 * lane + 1];
    float dot = a0.x * b0.x + a0.y * b0.y + a0.z * b0.z + a0.w * b0.w
              + a1.x * b1.x + a1.y * b1.y + a1.z * b1.z + a1.w * b1.w;
    dot += __shfl_xor_sync(0xffffffffu, dot, 1);
    dot += __shfl_xor_sync(0xffffffffu, dot, 2);
    if ((lane & 3) == 0) {
        int h = lane >> 2;
        float a = g_al[s * HEADS + h] + g_ar[d * HEADS + h];
        float sg = 1.f / (1.f + __expf(-dot));
        a *= sg;
        a = a > 0.f ? a : 0.2f * a;
        g_alpha[warp * HEADS + h] = a;
        atomicMax(&g_amax[d * HEADS + h], enc_f(a));
    }
}

// ---------------- aggregation with inline softmax (CSR, block per dst) ----------------
// mode 1: write elu(acc+b) into g_x1 ; mode 0: write acc+b into g_out2
// Denominator accumulated in registers (identical across lanes of a warp);
// exp cost is per warp-instruction so lane redundancy is free.
__global__ void aggregate_kernel(const float* __restrict__ b, int mode) {
    int v = blockIdx.x;
    int tid = threadIdx.x;
    int hh = tid >> 5;
    float amax = dec_f(g_amax[v * HEADS + hh]);
    int i = g_rowptr[v], end = g_rowptr[v + 1];
    float acc0 = 0.f, acc1 = 0.f, den = 0.f;
    for (; i + 1 < end; i += 2) {
        int sA = g_srcs[i],     eA = g_eids[i];
        int sB = g_srcs[i + 1], eB = g_eids[i + 1];
        float wA = __expf(g_alpha[eA * HEADS + hh] - amax);
        float wB = __expf(g_alpha[eB * HEADS + hh] - amax);
        acc0 += g_h[(long)sA * HC + tid] * wA;
        acc1 += g_h[(long)sB * HC + tid] * wB;
        den += wA + wB;
    }
    if (i < end) {
        int sA = g_srcs[i], eA = g_eids[i];
        float wA = __expf(g_alpha[eA * HEADS + hh] - amax);
        acc0 += g_h[(long)sA * HC + tid] * wA;
        den += wA;
    }
    float r = (acc0 + acc1) / (den + 1e-16f) + b[tid];
    if (mode) {
        r = r > 0.f ? r : expm1f(r);
        g_x1[(long)v * HC + tid] = r;
    } else {
        g_out2[(long)v * HC + tid] = r;
    }
}

// ---------------- pooling (sorted batch, binary search) ----------------
__device__ __forceinline__ int lbound_idx(const void* a, int n, int key) {
    int lo = 0, hi = n;
    while (lo < hi) {
        int mid = (lo + hi) >> 1;
        if (idx_at(a, mid) < key) lo = mid + 1; else hi = mid;
    }
    return lo;
}
__global__ void pool_kernel(const void* __restrict__ batch) {
    int g = blockIdx.x;
    int tid = threadIdx.x;
    int lo = lbound_idx(batch, NN, g);
    int hi = lbound_idx(batch, NN, g + 1);
    float acc = 0.f;
    for (int n = lo; n < hi; n++) acc += g_out2[(long)n * HC + tid];
    g_sums[g * HC + tid] = acc;
    if (tid == 0) g_cnt[g] = hi - lo;
}

// ---------------- final linear ----------------
__global__ void final_kernel(const float* __restrict__ linW, const float* __restrict__ linb,
                             float* __restrict__ out) {
    int g = blockIdx.x;
    int tid = threadIdx.x;
    int lane = tid & 31, w = tid >> 5;
    __shared__ float sw[8][CLS];
    float cnt = fmaxf((float)g_cnt[g], 1.f);
    float v = g_sums[g * HC + tid] / cnt;
    #pragma unroll
    for (int c = 0; c < CLS; c++) {
        float t = v * linW[tid * CLS + c];
        #pragma unroll
        for (int o = 16; o; o >>= 1) t += __shfl_xor_sync(0xffffffffu, t, o);
        if (lane == 0) sw[w][c] = t;
    }
    __syncthreads();
    if (tid < CLS) {
        float s = 0.f;
        #pragma unroll
        for (int ww = 0; ww < 8; ww++) s += sw[ww][tid];
        out[g * CLS + tid] = s + linb[tid];
    }
}

// ---------------- launch ----------------
extern "C" void kernel_launch(void* const* d_in, const int* in_sizes, int n_in,
                              void* d_out, int out_size) {
    const float* x = nullptr;
    const void*  ei = nullptr;
    const void*  batch = nullptr;
    const float *W1 = nullptr, *W2 = nullptr, *linW = nullptr, *linb = nullptr;
    const float* p256[6] = {};
    int n256 = 0;
    for (int i = 0; i < n_in; i++) {
        switch (in_sizes[i]) {
            case NN * FIN: x    = (const float*)d_in[i]; break;
            case 2 * EE:   ei   = d_in[i];               break;
            case NN:       batch = d_in[i];              break;
            case FIN * HC: W1   = (const float*)d_in[i]; break;
            case HC * HC:  W2   = (const float*)d_in[i]; break;
            case HC * CLS: linW = (const float*)d_in[i]; break;
            case CLS:      linb = (const float*)d_in[i]; break;
            case HC:       if (n256 < 6) p256[n256++] = (const float*)d_in[i]; break;
            default: break;
        }
    }
    const float* att_l1 = p256[0];
    const float* att_r1 = p256[1];
    const float* b1     = p256[2];
    const float* att_l2 = p256[3];
    const float* att_r2 = p256[4];
    const float* b2     = p256[5];
    float* out = (float*)d_out;
    (void)out_size;

    const int T = 256;
    dim3 ggrid(HC / BN, (NN + BM - 1) / BM);

    detect_kernel<<<1, 1>>>(ei);

    // CSR build (shared by both layers)
    zero_csr_kernel<<<(NN + T - 1) / T, T>>>();
    degree_kernel<<<(ETOT + T - 1) / T, T>>>(ei);
    scan_kernel<<<1, 1024>>>();
    scatter_kernel<<<(ETOT + T - 1) / T, T>>>(ei);

    // ---- layer 1 ----
    gemm_h_kernel<<<ggrid, 256>>>(x, W1, NN, FIN, 0);
    zero_amax_kernel<<<(NN * HEADS + T - 1) / T, T>>>();
    alr_kernel<<<(NN * 32 + T - 1) / T, T>>>(att_l1, att_r1);
    edge_alpha_kernel<<<(ETOT * 32 + T - 1) / T, T>>>(ei);
    aggregate_kernel<<<NN, 256>>>(b1, 1);

    // ---- layer 2 ----
    gemm_h_kernel<<<ggrid, 256>>>(nullptr, W2, NN, HC, 1);
    zero_amax_kernel<<<(NN * HEADS + T - 1) / T, T>>>();
    alr_kernel<<<(NN * 32 + T - 1) / T, T>>>(att_l2, att_r2);
    edge_alpha_kernel<<<(ETOT * 32 + T - 1) / T, T>>>(ei);
    aggregate_kernel<<<NN, 256>>>(b2, 0);

    // ---- pool + classify ----
    pool_kernel<<<GG, HC>>>(batch);
    final_kernel<<<GG, HC>>>(linW, linb, out);
}